// round 11
// baseline (speedup 1.0000x reference)
#include <cuda_runtime.h>

// FLoss: mean((1 - output[i, target[i]])^2)
// output: f32 [N,2]; target: int32 [N]. HBM-bound: 192 MiB in, 4 B out.
// 256-bit loads (sm_103a ld.global.v8): unit = 8 rows = 2x32B out + 1x32B tgt.
// 2048 blocks x 256 -> exactly 4 units/thread -> unroll-2 = 2 clean trips.

#define NBLOCKS 2048
#define NTHREADS 256

__device__ float        g_partials[NBLOCKS];
__device__ unsigned int g_done_count = 0;  // atomicInc wraps to 0 -> replay-safe

struct F8 { float4 lo, hi; };

__device__ __forceinline__ F8 ldg256f_cs(const float* p) {
    F8 r;
    asm volatile("ld.global.cs.v8.f32 {%0,%1,%2,%3,%4,%5,%6,%7}, [%8];"
                 : "=f"(r.lo.x), "=f"(r.lo.y), "=f"(r.lo.z), "=f"(r.lo.w),
                   "=f"(r.hi.x), "=f"(r.hi.y), "=f"(r.hi.z), "=f"(r.hi.w)
                 : "l"(p));
    return r;
}

__device__ __forceinline__ void ldg256i_cs(const int* p, int t[8]) {
    asm volatile("ld.global.cs.v8.b32 {%0,%1,%2,%3,%4,%5,%6,%7}, [%8];"
                 : "=r"(t[0]), "=r"(t[1]), "=r"(t[2]), "=r"(t[3]),
                   "=r"(t[4]), "=r"(t[5]), "=r"(t[6]), "=r"(t[7])
                 : "l"(p));
}

// 8 rows: o0 = rows r..r+3 (2 floats each), o1 = rows r+4..r+7, t[8] targets.
__device__ __forceinline__ float oct_term(F8 o0, F8 o1, const int t[8]) {
    float x0 = (t[0] == 0) ? o0.lo.x : o0.lo.y;
    float x1 = (t[1] == 0) ? o0.lo.z : o0.lo.w;
    float x2 = (t[2] == 0) ? o0.hi.x : o0.hi.y;
    float x3 = (t[3] == 0) ? o0.hi.z : o0.hi.w;
    float x4 = (t[4] == 0) ? o1.lo.x : o1.lo.y;
    float x5 = (t[5] == 0) ? o1.lo.z : o1.lo.w;
    float x6 = (t[6] == 0) ? o1.hi.x : o1.hi.y;
    float x7 = (t[7] == 0) ? o1.hi.z : o1.hi.w;
    float d0 = 1.0f - x0, d1 = 1.0f - x1, d2 = 1.0f - x2, d3 = 1.0f - x3;
    float d4 = 1.0f - x4, d5 = 1.0f - x5, d6 = 1.0f - x6, d7 = 1.0f - x7;
    float s0 = fmaf(d0, d0, d1 * d1);
    float s1 = fmaf(d2, d2, d3 * d3);
    float s2 = fmaf(d4, d4, d5 * d5);
    float s3 = fmaf(d6, d6, d7 * d7);
    return (s0 + s1) + (s2 + s3);
}

__device__ __forceinline__ float block_reduce(float acc, float* warp_sums) {
    #pragma unroll
    for (int off = 16; off > 0; off >>= 1)
        acc += __shfl_xor_sync(0xFFFFFFFFu, acc, off);
    int lane = threadIdx.x & 31;
    int wid  = threadIdx.x >> 5;
    if (lane == 0) warp_sums[wid] = acc;
    __syncthreads();
    float v = 0.0f;
    if (wid == 0) {
        v = (lane < NTHREADS / 32) ? warp_sums[lane] : 0.0f;
        #pragma unroll
        for (int off = 4; off > 0; off >>= 1)
            v += __shfl_xor_sync(0xFFFFFFFFu, v, off);
    }
    return v;  // valid in warp 0 lane 0
}

__global__ __launch_bounds__(NTHREADS)
void floss_v8_kernel(const float* __restrict__ out,
                     const int* __restrict__ tgt,
                     int nu /* = N/8 */,
                     float inv_n,
                     float* __restrict__ d_out) {
    float acc = 0.0f;
    int j = blockIdx.x * NTHREADS + threadIdx.x;
    const int stride = NBLOCKS * NTHREADS;

    // Unroll-by-2: 6 independent 32B loads in flight per thread.
    // For N=16.7M: exactly 2 trips, remainder empty.
    for (; j + stride < nu; j += 2 * stride) {
        int k = j + stride;
        F8 a0 = ldg256f_cs(out + 16 * (size_t)j);
        F8 a1 = ldg256f_cs(out + 16 * (size_t)j + 8);
        F8 b0 = ldg256f_cs(out + 16 * (size_t)k);
        F8 b1 = ldg256f_cs(out + 16 * (size_t)k + 8);
        int ta[8], tb[8];
        ldg256i_cs(tgt + 8 * (size_t)j, ta);
        ldg256i_cs(tgt + 8 * (size_t)k, tb);
        acc += oct_term(a0, a1, ta);
        acc += oct_term(b0, b1, tb);
    }
    // Remainder (empty at the benchmark shape)
    for (; j < nu; j += stride) {
        F8 a0 = ldg256f_cs(out + 16 * (size_t)j);
        F8 a1 = ldg256f_cs(out + 16 * (size_t)j + 8);
        int ta[8];
        ldg256i_cs(tgt + 8 * (size_t)j, ta);
        acc += oct_term(a0, a1, ta);
    }

    __shared__ float warp_sums[NTHREADS / 32];
    float bsum = block_reduce(acc, warp_sums);

    __shared__ bool is_last;
    if (threadIdx.x == 0) {
        g_partials[blockIdx.x] = bsum;
        __threadfence();
        unsigned int prev = atomicInc(&g_done_count, NBLOCKS - 1);
        is_last = (prev == NBLOCKS - 1);
    }
    __syncthreads();

    if (is_last) {
        float facc = 0.0f;
        for (int i = threadIdx.x; i < NBLOCKS; i += NTHREADS)
            facc += g_partials[i];
        __syncthreads();  // warp_sums reuse safe
        float total = block_reduce(facc, warp_sums);
        if (threadIdx.x == 0) d_out[0] = total * inv_n;
    }
}

extern "C" void kernel_launch(void* const* d_in, const int* in_sizes, int n_in,
                              void* d_out, int out_size) {
    const float* output = (const float*)d_in[0];  // [N, 2] f32
    const int*   target = (const int*)d_in[1];    // [N] int32

    long long n = (long long)in_sizes[1];  // N
    int nu = (int)(n / 8);                 // groups of 8 rows

    floss_v8_kernel<<<NBLOCKS, NTHREADS>>>(output, target, nu,
                                           1.0f / (float)n, (float*)d_out);
}